// round 2
// baseline (speedup 1.0000x reference)
#include <cuda_runtime.h>

// Problem constants
#define BB   2
#define SS   2048
#define HID  1024
#define NH   16
#define DH   64
#define ROT  32

// Scratch (device globals; no allocations allowed)
__device__ float g_Q[BB * NH * SS * DH];   // query, rotary+scale applied, [b][h][s][d]
__device__ float g_K[BB * NH * SS * DH];   // key, rotary applied
__device__ float g_V[BB * NH * SS * DH];   // value
__device__ float g_ctx[BB * SS * HID];     // attention output, [b][s][h*64+d]

// ---------------------------------------------------------------------------
// Kernel 1: QKV GEMM  x[4096,1024] @ w[1024,3072] -> fused bias+rotary+scatter
// ---------------------------------------------------------------------------
__global__ __launch_bounds__(256) void qkv_gemm_kernel(
    const float* __restrict__ x, const float* __restrict__ w,
    const float* __restrict__ qbias, const float* __restrict__ sinu)
{
    __shared__ float As[16][68];   // [k][m], padded
    __shared__ float Bs[16][64];   // [k][n]
    const int tid = threadIdx.x, ty = tid >> 4, tx = tid & 15;
    const int bm = blockIdx.y * 64, bn = blockIdx.x * 64;
    const int N = 3 * NH * DH;     // 3072
    const int K = HID;             // 1024

    float acc[4][4] = {};

    for (int k0 = 0; k0 < K; k0 += 16) {
        #pragma unroll
        for (int t = 0; t < 4; ++t) {
            int idx = tid + t * 256;
            int r = idx >> 4, c = idx & 15;
            As[c][r] = x[(size_t)(bm + r) * K + k0 + c];
        }
        {
            int kr = tid >> 4, c4 = tid & 15;
            ((float4*)&Bs[kr][0])[c4] =
                ((const float4*)&w[(size_t)(k0 + kr) * N + bn])[c4];
        }
        __syncthreads();
        #pragma unroll
        for (int k = 0; k < 16; ++k) {
            float4 a4 = *(const float4*)&As[k][ty * 4];
            float4 b4 = *(const float4*)&Bs[k][tx * 4];
            float av[4] = {a4.x, a4.y, a4.z, a4.w};
            float bv[4] = {b4.x, b4.y, b4.z, b4.w};
            #pragma unroll
            for (int i = 0; i < 4; ++i)
                #pragma unroll
                for (int j = 0; j < 4; ++j)
                    acc[i][j] += av[i] * bv[j];
        }
        __syncthreads();
    }

    // Epilogue: bias + rotary (+ query scale), scatter to Q/K/V
    const int head = bn >> 6;  // constant per block (bn multiple of 64)
    #pragma unroll
    for (int i = 0; i < 4; ++i) {
        int m = bm + ty * 4 + i;
        int b = m >> 11;            // m / SS
        int s = m & (SS - 1);
        #pragma unroll
        for (int j = 0; j < 4; ++j) {
            int d = tx * 4 + j;
            float v = acc[i][j] + qbias[head * DH + d];
            if (head < 2 * NH && d < ROT) {
                float sn = sinu[s * ROT + d];
                float cs = sinu[SS * ROT + s * ROT + d];
                v *= (d & 1) ? (cs + sn) : (cs - sn);
            }
            if (head < NH) {
                g_Q[(((size_t)(b * NH + head) * SS) + s) * DH + d] = v * 0.125f;
            } else if (head < 2 * NH) {
                g_K[(((size_t)(b * NH + head - NH) * SS) + s) * DH + d] = v;
            } else {
                g_V[(((size_t)(b * NH + head - 2 * NH) * SS) + s) * DH + d] = v;
            }
        }
    }
}

// ---------------------------------------------------------------------------
// Kernel 2: flash attention. CTA = (q-tile of 64, head, batch). 256 threads.
// Thread (ty,tx): rows ty*4+i, cols tx+16*j.
// SMEM: Qs[64][68], Ks[64][68] (reused for P), Vs[64][68]  -> 52224 B dynamic
// ---------------------------------------------------------------------------
__global__ __launch_bounds__(256) void flash_kernel(const float* __restrict__ bias)
{
    extern __shared__ float sm[];
    float* Qs = sm;                // [64][68]
    float* Ks = sm + 64 * 68;      // [64][68], later holds P
    float* Vs = sm + 2 * 64 * 68;  // [64][68]

    const int tid = threadIdx.x, ty = tid >> 4, tx = tid & 15;
    const int qt = blockIdx.x, h = blockIdx.y, b = blockIdx.z;

    const float* Qg = g_Q + ((size_t)(b * NH + h) * SS + qt * 64) * DH;
    const float* Kg = g_K + (size_t)(b * NH + h) * SS * DH;
    const float* Vg = g_V + (size_t)(b * NH + h) * SS * DH;
    const float* bg = bias + ((size_t)b * SS + qt * 64) * SS;

    // Load Q tile
    {
        const float4* q4 = (const float4*)Qg;
        #pragma unroll
        for (int t = 0; t < 4; ++t) {
            int idx = tid + t * 256;
            int r = idx >> 4, c = idx & 15;
            *(float4*)&Qs[r * 68 + c * 4] = q4[idx];
        }
    }

    float m_i[4], l_i[4], o[4][4];
    #pragma unroll
    for (int i = 0; i < 4; ++i) {
        m_i[i] = -1e30f; l_i[i] = 0.f;
        #pragma unroll
        for (int j = 0; j < 4; ++j) o[i][j] = 0.f;
    }

    for (int kt = 0; kt < SS / 64; ++kt) {
        __syncthreads();  // previous iteration done with Ks(P)/Vs
        {
            const float4* k4 = (const float4*)(Kg + (size_t)kt * 64 * DH);
            const float4* v4 = (const float4*)(Vg + (size_t)kt * 64 * DH);
            #pragma unroll
            for (int t = 0; t < 4; ++t) {
                int idx = tid + t * 256;
                int r = idx >> 4, c = idx & 15;
                *(float4*)&Ks[r * 68 + c * 4] = k4[idx];
                *(float4*)&Vs[r * 68 + c * 4] = v4[idx];
            }
        }
        __syncthreads();

        // s = bias + q.k  (scale pre-folded into Q)
        float s[4][4];
        #pragma unroll
        for (int i = 0; i < 4; ++i)
            #pragma unroll
            for (int j = 0; j < 4; ++j)
                s[i][j] = __ldg(&bg[(size_t)(ty * 4 + i) * SS + kt * 64 + tx + 16 * j]);

        #pragma unroll 8
        for (int d = 0; d < 64; ++d) {
            float qv[4], kv[4];
            #pragma unroll
            for (int i = 0; i < 4; ++i) qv[i] = Qs[(ty * 4 + i) * 68 + d];
            #pragma unroll
            for (int j = 0; j < 4; ++j) kv[j] = Ks[(tx + 16 * j) * 68 + d];
            #pragma unroll
            for (int i = 0; i < 4; ++i)
                #pragma unroll
                for (int j = 0; j < 4; ++j)
                    s[i][j] += qv[i] * kv[j];
        }

        // online softmax (row reductions across the 16 tx lanes)
        #pragma unroll
        for (int i = 0; i < 4; ++i) {
            float mx = fmaxf(fmaxf(s[i][0], s[i][1]), fmaxf(s[i][2], s[i][3]));
            #pragma unroll
            for (int w = 1; w < 16; w <<= 1)
                mx = fmaxf(mx, __shfl_xor_sync(0xffffffffu, mx, w));
            float mnew = fmaxf(m_i[i], mx);
            float ps = 0.f;
            #pragma unroll
            for (int j = 0; j < 4; ++j) {
                s[i][j] = __expf(s[i][j] - mnew);
                ps += s[i][j];
            }
            #pragma unroll
            for (int w = 1; w < 16; w <<= 1)
                ps += __shfl_xor_sync(0xffffffffu, ps, w);
            float corr = __expf(m_i[i] - mnew);
            l_i[i] = l_i[i] * corr + ps;
            m_i[i] = mnew;
            #pragma unroll
            for (int j = 0; j < 4; ++j) o[i][j] *= corr;
        }

        __syncthreads();  // everyone done reading Ks
        #pragma unroll
        for (int i = 0; i < 4; ++i)
            #pragma unroll
            for (int j = 0; j < 4; ++j)
                Ks[(ty * 4 + i) * 68 + tx + 16 * j] = s[i][j];   // P tile
        __syncthreads();

        // o += P @ V
        #pragma unroll 8
        for (int k = 0; k < 64; ++k) {
            float pv[4], vv[4];
            #pragma unroll
            for (int i = 0; i < 4; ++i) pv[i] = Ks[(ty * 4 + i) * 68 + k];
            #pragma unroll
            for (int j = 0; j < 4; ++j) vv[j] = Vs[k * 68 + tx + 16 * j];
            #pragma unroll
            for (int i = 0; i < 4; ++i)
                #pragma unroll
                for (int j = 0; j < 4; ++j)
                    o[i][j] += pv[i] * vv[j];
        }
    }

    // normalize and write ctx as [b][s][h][d]
    #pragma unroll
    for (int i = 0; i < 4; ++i) {
        float inv = 1.0f / l_i[i];
        int q = qt * 64 + ty * 4 + i;
        float* dst = g_ctx + ((size_t)(b * SS + q) * NH + h) * DH;
        #pragma unroll
        for (int j = 0; j < 4; ++j)
            dst[tx + 16 * j] = o[i][j] * inv;
    }
}

// ---------------------------------------------------------------------------
// Kernel 3: output projection  ctx[4096,1024] @ proj[1024,1024] -> out
// ---------------------------------------------------------------------------
__global__ __launch_bounds__(256) void proj_gemm_kernel(
    const float* __restrict__ w, float* __restrict__ out)
{
    __shared__ float As[16][68];
    __shared__ float Bs[16][64];
    const int tid = threadIdx.x, ty = tid >> 4, tx = tid & 15;
    const int bm = blockIdx.y * 64, bn = blockIdx.x * 64;
    const int N = HID, K = HID;

    float acc[4][4] = {};

    for (int k0 = 0; k0 < K; k0 += 16) {
        #pragma unroll
        for (int t = 0; t < 4; ++t) {
            int idx = tid + t * 256;
            int r = idx >> 4, c = idx & 15;
            As[c][r] = g_ctx[(size_t)(bm + r) * K + k0 + c];
        }
        {
            int kr = tid >> 4, c4 = tid & 15;
            ((float4*)&Bs[kr][0])[c4] =
                ((const float4*)&w[(size_t)(k0 + kr) * N + bn])[c4];
        }
        __syncthreads();
        #pragma unroll
        for (int k = 0; k < 16; ++k) {
            float4 a4 = *(const float4*)&As[k][ty * 4];
            float4 b4 = *(const float4*)&Bs[k][tx * 4];
            float av[4] = {a4.x, a4.y, a4.z, a4.w};
            float bv[4] = {b4.x, b4.y, b4.z, b4.w};
            #pragma unroll
            for (int i = 0; i < 4; ++i)
                #pragma unroll
                for (int j = 0; j < 4; ++j)
                    acc[i][j] += av[i] * bv[j];
        }
        __syncthreads();
    }

    #pragma unroll
    for (int i = 0; i < 4; ++i) {
        float4 r = make_float4(acc[i][0], acc[i][1], acc[i][2], acc[i][3]);
        *(float4*)&out[(size_t)(bm + ty * 4 + i) * N + bn + tx * 4] = r;
    }
}

// ---------------------------------------------------------------------------
extern "C" void kernel_launch(void* const* d_in, const int* in_sizes, int n_in,
                              void* d_out, int out_size)
{
    const float* x      = (const float*)d_in[0];
    const float* sinu   = (const float*)d_in[1];
    const float* abias  = (const float*)d_in[2];
    const float* qkv_w  = (const float*)d_in[3];
    const float* qkv_b  = (const float*)d_in[4];
    const float* proj_w = (const float*)d_in[5];
    float* out = (float*)d_out;

    const int flash_smem = 3 * 64 * 68 * (int)sizeof(float);  // 52224 B
    cudaFuncSetAttribute(flash_kernel,
                         cudaFuncAttributeMaxDynamicSharedMemorySize, flash_smem);

    dim3 blk(256);
    qkv_gemm_kernel<<<dim3(48, 64), blk>>>(x, qkv_w, qkv_b, sinu);
    flash_kernel<<<dim3(SS / 64, NH, BB), blk, flash_smem>>>(abias);
    proj_gemm_kernel<<<dim3(16, 64), blk>>>(proj_w, out);
}